// round 6
// baseline (speedup 1.0000x reference)
#include <cuda_runtime.h>

#define NROWS 14400   // bs * Q = 16 * 900
#define NCLS  128
#define NTGT  3200
#define BT    128     // targets per block
#define BR    32      // rows per block

typedef unsigned long long u64;

// Scratch (no allocations allowed) ------------------------------------------
__device__ __align__(16) float  g_ccost[NROWS * NCLS];   // (focal class cost + 2), 7.37 MB
__device__ __align__(16) float4 g_txyxy[NTGT];           // x0,y0,x1,y1
__device__ __align__(16) float4 g_tneg[NTGT];            // -cx,-cy,-w,-h
__device__ __align__(16) float2 g_tmeta[NTGT];           // area, class-bits

// ---- packed f32x2 helpers (Blackwell) -------------------------------------
__device__ __forceinline__ u64 pk2(float lo, float hi) {
    u64 r; asm("mov.b64 %0,{%1,%2};" : "=l"(r) : "f"(lo), "f"(hi)); return r;
}
__device__ __forceinline__ float2 upk2(u64 v) {
    float2 f; asm("mov.b64 {%0,%1},%2;" : "=f"(f.x), "=f"(f.y) : "l"(v)); return f;
}
__device__ __forceinline__ u64 padd(u64 a, u64 b) {
    u64 r; asm("add.rn.f32x2 %0,%1,%2;" : "=l"(r) : "l"(a), "l"(b)); return r;
}
__device__ __forceinline__ float frcp(float x) {
    float r; asm("rcp.approx.f32 %0,%1;" : "=f"(r) : "f"(x)); return r;
}

// ---------------------------------------------------------------------------
// Kernel 1 (fused): row softmax + focal table (+2 folded), and target precompute.
// Blocks [0,1800): 8 warps = 8 rows each. Blocks [1800,1813): targets.
// ---------------------------------------------------------------------------
__device__ __forceinline__ float focal_cc2(float p) {
    float ip  = 1.0f - p;
    float pos = 0.25f * ip * ip * (-__logf(p  + 1e-8f));
    float neg = 0.75f * p  * p  * (-__logf(ip + 1e-8f));
    return pos - neg + 2.0f;          // +2 from the GIoU algebra folded in
}

__global__ void prep(const float* __restrict__ logits,
                     const float* __restrict__ tbox,
                     const int*   __restrict__ tids) {
    if (blockIdx.x < 1800) {
        int warp = blockIdx.x * 8 + (threadIdx.x >> 5);
        int lane = threadIdx.x & 31;

        const float4* lrow = (const float4*)(logits + (size_t)warp * NCLS);
        float4 l = lrow[lane];

        float m = fmaxf(fmaxf(l.x, l.y), fmaxf(l.z, l.w));
        #pragma unroll
        for (int o = 16; o > 0; o >>= 1) m = fmaxf(m, __shfl_xor_sync(0xffffffffu, m, o));

        float ex = __expf(l.x - m), ey = __expf(l.y - m);
        float ez = __expf(l.z - m), ew = __expf(l.w - m);
        float s = ex + ey + ez + ew;
        #pragma unroll
        for (int o = 16; o > 0; o >>= 1) s += __shfl_xor_sync(0xffffffffu, s, o);
        float rs = __fdividef(1.0f, s);

        float4 cc;
        cc.x = focal_cc2(ex * rs);
        cc.y = focal_cc2(ey * rs);
        cc.z = focal_cc2(ez * rs);
        cc.w = focal_cc2(ew * rs);
        ((float4*)(g_ccost + (size_t)warp * NCLS))[lane] = cc;
    } else {
        int i = (blockIdx.x - 1800) * 256 + threadIdx.x;
        if (i >= NTGT) return;
        float4 b = ((const float4*)tbox)[i];
        float hw = 0.5f * b.z, hh = 0.5f * b.w;
        g_txyxy[i] = make_float4(b.x - hw, b.y - hh, b.x + hw, b.y + hh);
        g_tneg[i]  = make_float4(-b.x, -b.y, -b.z, -b.w);
        int c = min(max(tids[i], 0), NCLS - 1);
        g_tmeta[i] = make_float2(b.z * b.w, __int_as_float(c));
    }
}

// ---------------------------------------------------------------------------
// Kernel 2: main cost matrix. Grid (NTGT/BT, NROWS/BR), 256 threads.
// Thread tile: 4 rows x 4 targets; tx = 4 contiguous targets (STG.128).
// ---------------------------------------------------------------------------
__global__ void __launch_bounds__(256)
cost_main(const float* __restrict__ pboxes,
          float* __restrict__ out) {
    __shared__ float  s_cc[BR * NCLS];   // 16 KB class-cost(+2) tables
    __shared__ float4 s_txyxy[BT];
    __shared__ float4 s_tneg[BT];
    __shared__ float2 s_tmeta[BT];

    int tid = threadIdx.x;
    int tb  = blockIdx.x * BT;
    int rb  = blockIdx.y * BR;

    {   // 32*128 floats = 1024 float4, 4 per thread
        const float4* src = (const float4*)(g_ccost + (size_t)rb * NCLS);
        float4* dst = (float4*)s_cc;
        #pragma unroll
        for (int i = 0; i < 4; i++) dst[tid + i * 256] = src[tid + i * 256];
    }
    if (tid < BT) {
        s_txyxy[tid] = g_txyxy[tb + tid];
        s_tneg[tid]  = g_tneg[tb + tid];
        s_tmeta[tid] = g_tmeta[tb + tid];
    }
    __syncthreads();

    int tx = tid & 31, ty = tid >> 5;
    int r0 = rb + ty * 4;
    int t0 = tx * 4;

    // Row operands (4 rows)
    float rx0[4], ry0[4], rx1[4], ry1[4], ra[4];
    u64   prc[4], prwh[4];
    #pragma unroll
    for (int i = 0; i < 4; i++) {
        float4 b = ((const float4*)pboxes)[r0 + i];
        float hw = 0.5f * b.z, hh = 0.5f * b.w;
        rx0[i] = b.x - hw; ry0[i] = b.y - hh;
        rx1[i] = b.x + hw; ry1[i] = b.y + hh;
        ra[i]  = b.z * b.w;
        prc[i]  = pk2(b.x, b.y);
        prwh[i] = pk2(b.z, b.w);
    }

    // Target operands (4 targets)
    float tX0[4], tY0[4], tX1[4], tY1[4], ta[4];
    int   tcl[4];
    u64   pnc[4], pnwh[4];
    #pragma unroll
    for (int j = 0; j < 4; j++) {
        float4 x = s_txyxy[t0 + j];
        tX0[j] = x.x; tY0[j] = x.y; tX1[j] = x.z; tY1[j] = x.w;
        float4 n = s_tneg[t0 + j];
        pnc[j]  = pk2(n.x, n.y);
        pnwh[j] = pk2(n.z, n.w);
        float2 mt = s_tmeta[t0 + j];
        ta[j]  = mt.x;
        tcl[j] = __float_as_int(mt.y);
    }

    #pragma unroll
    for (int i = 0; i < 4; i++) {
        float4 o;
        float* op = &o.x;
        const float* ccrow = s_cc + (ty * 4 + i) * NCLS;
        #pragma unroll
        for (int j = 0; j < 4; j++) {
            float cc = ccrow[tcl[j]];                 // (class cost + 2)

            // L1 (packed diffs; abs folds into the FADD sum as modifiers)
            float2 e1 = upk2(padd(prc[i],  pnc[j]));
            float2 e2 = upk2(padd(prwh[i], pnwh[j]));
            float l1 = (fabsf(e1.x) + fabsf(e1.y)) + (fabsf(e2.x) + fabsf(e2.y));

            // intersection: -lt via FMNMX with free neg modifiers
            float nltx = fminf(-rx0[i], -tX0[j]);
            float nlty = fminf(-ry0[i], -tY0[j]);
            float rbx  = fminf(rx1[i], tX1[j]);
            float rby  = fminf(ry1[i], tY1[j]);
            float iw   = fmaxf(rbx + nltx, 0.0f);
            float ih   = fmaxf(rby + nlty, 0.0f);
            float inter = iw * ih;
            float uni   = (ra[i] + ta[j]) - inter;

            // enclosing box: -li via FMNMX neg modifiers
            float nlix = fmaxf(-rx0[i], -tX0[j]);
            float nliy = fmaxf(-ry0[i], -tY0[j]);
            float rix  = fmaxf(rx1[i], tX1[j]);
            float riy  = fmaxf(ry1[i], tY1[j]);
            float ai   = (rix + nlix) * (riy + nliy);

            // C = 5*l1 + (cc+2) - 2*inter/uni - 2*uni/ai
            float r1 = frcp(uni);
            float r2 = frcp(ai);
            float iou = inter * r1;
            float q   = uni * r2;
            float res = fmaf(l1, 5.0f, cc);      // FFMA-imm (rt 1)
            res = fmaf(iou, -2.0f, res);         // FFMA-imm
            res = fmaf(q,   -2.0f, res);         // FFMA-imm
            op[j] = res;
        }
        *((float4*)(out + (size_t)(r0 + i) * NTGT + tb + t0)) = o;
    }
}

// ---------------------------------------------------------------------------
extern "C" void kernel_launch(void* const* d_in, const int* in_sizes, int n_in,
                              void* d_out, int out_size) {
    const float* logits = (const float*)d_in[0];      // [16,900,128]
    const float* pboxes = (const float*)d_in[1];      // [16,900,4]
    const int*   tids   = (const int*)d_in[2];        // [3200] int32
    const float* tbox   = (const float*)d_in[3];      // [3200,4]
    float* out = (float*)d_out;                       // [16,900,3200]

    prep<<<1800 + (NTGT + 255) / 256, 256>>>(logits, tbox, tids);

    dim3 grid(NTGT / BT, NROWS / BR);                 // (25, 450)
    cost_main<<<grid, 256>>>(pboxes, out);
}

// round 7
// speedup vs baseline: 1.1387x; 1.1387x over previous
#include <cuda_runtime.h>

#define NROWS 14400   // bs * Q = 16 * 900
#define NCLS  128
#define NTGT  3200
#define BT    128     // targets per block
#define BR    32      // rows per block

// Scratch (no allocations allowed) ------------------------------------------
__device__ __align__(16) float  g_ccost[NROWS * NCLS];   // (focal class cost + 2), 7.37 MB
__device__ __align__(16) float4 g_txyxy[NTGT];           // x0,y0,x1,y1
__device__ __align__(16) float4 g_tcwh[NTGT];            // cx,cy,w,h
__device__ __align__(16) float2 g_tmeta[NTGT];           // area, class-bits

__device__ __forceinline__ float frcp(float x) {
    float r; asm("rcp.approx.f32 %0,%1;" : "=f"(r) : "f"(x)); return r;
}

// ---------------------------------------------------------------------------
// Kernel 1 (fused): row softmax + focal table (+2 folded), and target precompute.
// Blocks [0,1800): 8 warps = 8 rows each. Blocks [1800,1813): targets.
// ---------------------------------------------------------------------------
__device__ __forceinline__ float focal_cc2(float p) {
    float ip  = 1.0f - p;
    float pos = 0.25f * ip * ip * (-__logf(p  + 1e-8f));
    float neg = 0.75f * p  * p  * (-__logf(ip + 1e-8f));
    return pos - neg + 2.0f;          // +2 from the GIoU algebra folded in
}

__global__ void prep(const float* __restrict__ logits,
                     const float* __restrict__ tbox,
                     const int*   __restrict__ tids) {
    if (blockIdx.x < 1800) {
        int warp = blockIdx.x * 8 + (threadIdx.x >> 5);
        int lane = threadIdx.x & 31;

        const float4* lrow = (const float4*)(logits + (size_t)warp * NCLS);
        float4 l = lrow[lane];

        float m = fmaxf(fmaxf(l.x, l.y), fmaxf(l.z, l.w));
        #pragma unroll
        for (int o = 16; o > 0; o >>= 1) m = fmaxf(m, __shfl_xor_sync(0xffffffffu, m, o));

        float ex = __expf(l.x - m), ey = __expf(l.y - m);
        float ez = __expf(l.z - m), ew = __expf(l.w - m);
        float s = ex + ey + ez + ew;
        #pragma unroll
        for (int o = 16; o > 0; o >>= 1) s += __shfl_xor_sync(0xffffffffu, s, o);
        float rs = __fdividef(1.0f, s);

        float4 cc;
        cc.x = focal_cc2(ex * rs);
        cc.y = focal_cc2(ey * rs);
        cc.z = focal_cc2(ez * rs);
        cc.w = focal_cc2(ew * rs);
        ((float4*)(g_ccost + (size_t)warp * NCLS))[lane] = cc;
    } else {
        int i = (blockIdx.x - 1800) * 256 + threadIdx.x;
        if (i >= NTGT) return;
        float4 b = ((const float4*)tbox)[i];
        float hw = 0.5f * b.z, hh = 0.5f * b.w;
        g_txyxy[i] = make_float4(b.x - hw, b.y - hh, b.x + hw, b.y + hh);
        g_tcwh[i]  = b;
        int c = min(max(tids[i], 0), NCLS - 1);
        g_tmeta[i] = make_float2(b.z * b.w, __int_as_float(c));
    }
}

// ---------------------------------------------------------------------------
// Kernel 2: main cost matrix. Grid (NTGT/BT, NROWS/BR), 256 threads.
// Thread tile: 4 rows x 4 targets; tx = 4 contiguous targets (STG.128).
// launch_bounds(256,4): cap regs at 64 -> 4 blocks/SM -> ~50% occupancy.
// ---------------------------------------------------------------------------
__global__ void __launch_bounds__(256, 4)
cost_main(const float* __restrict__ pboxes,
          float* __restrict__ out) {
    __shared__ float  s_cc[BR * NCLS];   // 16 KB class-cost(+2) tables
    __shared__ float4 s_txyxy[BT];
    __shared__ float4 s_tc[BT];
    __shared__ float2 s_tmeta[BT];

    int tid = threadIdx.x;
    int tb  = blockIdx.x * BT;
    int rb  = blockIdx.y * BR;

    {   // 32*128 floats = 1024 float4, 4 per thread
        const float4* src = (const float4*)(g_ccost + (size_t)rb * NCLS);
        float4* dst = (float4*)s_cc;
        #pragma unroll
        for (int i = 0; i < 4; i++) dst[tid + i * 256] = src[tid + i * 256];
    }
    if (tid < BT) {
        s_txyxy[tid] = g_txyxy[tb + tid];
        s_tc[tid]    = g_tcwh[tb + tid];
        s_tmeta[tid] = g_tmeta[tb + tid];
    }
    __syncthreads();

    int tx = tid & 31, ty = tid >> 5;
    int r0 = rb + ty * 4;
    int t0 = tx * 4;

    // Row operands (4 rows x 9 floats)
    float rcx[4], rcy[4], rw[4], rh[4];
    float rx0[4], ry0[4], rx1[4], ry1[4], ra[4];
    #pragma unroll
    for (int i = 0; i < 4; i++) {
        float4 b = ((const float4*)pboxes)[r0 + i];
        rcx[i] = b.x; rcy[i] = b.y; rw[i] = b.z; rh[i] = b.w;
        float hw = 0.5f * b.z, hh = 0.5f * b.w;
        rx0[i] = b.x - hw; ry0[i] = b.y - hh;
        rx1[i] = b.x + hw; ry1[i] = b.y + hh;
        ra[i]  = b.z * b.w;
    }

    // Target operands (4 targets)
    float tcx[4], tcy[4], tw[4], th[4];
    float tX0[4], tY0[4], tX1[4], tY1[4], ta[4];
    int   tcl[4];
    #pragma unroll
    for (int j = 0; j < 4; j++) {
        float4 c = s_tc[t0 + j];
        tcx[j] = c.x; tcy[j] = c.y; tw[j] = c.z; th[j] = c.w;
        float4 x = s_txyxy[t0 + j];
        tX0[j] = x.x; tY0[j] = x.y; tX1[j] = x.z; tY1[j] = x.w;
        float2 mt = s_tmeta[t0 + j];
        ta[j]  = mt.x;
        tcl[j] = __float_as_int(mt.y);
    }

    #pragma unroll
    for (int i = 0; i < 4; i++) {
        float4 o;
        float* op = &o.x;
        const float* ccrow = s_cc + (ty * 4 + i) * NCLS;
        #pragma unroll
        for (int j = 0; j < 4; j++) {
            float cc = ccrow[tcl[j]];                 // (class cost + 2)

            // L1 box cost (cxcywh space)
            float l1 = fabsf(rcx[i] - tcx[j]) + fabsf(rcy[i] - tcy[j])
                     + fabsf(rw[i]  - tw[j])  + fabsf(rh[i]  - th[j]);

            // intersection
            float ltx = fmaxf(rx0[i], tX0[j]);
            float lty = fmaxf(ry0[i], tY0[j]);
            float rbx = fminf(rx1[i], tX1[j]);
            float rby = fminf(ry1[i], tY1[j]);
            float iw  = fmaxf(rbx - ltx, 0.0f);
            float ih  = fmaxf(rby - lty, 0.0f);
            float inter = iw * ih;
            float uni   = (ra[i] + ta[j]) - inter;

            // enclosing box
            float lix = fminf(rx0[i], tX0[j]);
            float liy = fminf(ry0[i], tY0[j]);
            float rix = fmaxf(rx1[i], tX1[j]);
            float riy = fmaxf(ry1[i], tY1[j]);
            float ai  = (rix - lix) * (riy - liy);

            // C = 5*l1 + (cc+2) - 2*inter/uni - 2*uni/ai
            float iou = inter * frcp(uni);
            float q   = uni * frcp(ai);
            float res = fmaf(l1, 5.0f, cc);      // FFMA-imm (rt 1)
            res = fmaf(iou, -2.0f, res);         // FFMA-imm
            res = fmaf(q,   -2.0f, res);         // FFMA-imm
            op[j] = res;
        }
        *((float4*)(out + (size_t)(r0 + i) * NTGT + tb + t0)) = o;
    }
}

// ---------------------------------------------------------------------------
extern "C" void kernel_launch(void* const* d_in, const int* in_sizes, int n_in,
                              void* d_out, int out_size) {
    const float* logits = (const float*)d_in[0];      // [16,900,128]
    const float* pboxes = (const float*)d_in[1];      // [16,900,4]
    const int*   tids   = (const int*)d_in[2];        // [3200] int32
    const float* tbox   = (const float*)d_in[3];      // [3200,4]
    float* out = (float*)d_out;                       // [16,900,3200]

    prep<<<1800 + (NTGT + 255) / 256, 256>>>(logits, tbox, tids);

    dim3 grid(NTGT / BT, NROWS / BR);                 // (25, 450)
    cost_main<<<grid, 256>>>(pboxes, out);
}

// round 8
// speedup vs baseline: 1.3340x; 1.1714x over previous
#include <cuda_runtime.h>

#define NROWS 14400   // bs * Q
#define NCLS  128
#define NTGT  3200
#define BT    128     // targets per block
#define BR    32      // rows per block
#define RBLK  450     // NROWS / BR
#define CPAD  36      // padded row stride (floats) of transposed cc table

// Scratch (no allocations allowed) ------------------------------------------
__device__ __align__(16) float    g_ccostT[NROWS * NCLS]; // [450][128 cls][32 rows], (+2 folded)
__device__ __align__(16) float4   g_tcwh[NTGT];           // cx,cy,w,h
__device__ __align__(16) unsigned g_tcl4[NTGT / 4];       // 4 packed class bytes

__device__ __forceinline__ float frcp(float x) {
    float r; asm("rcp.approx.f32 %0,%1;" : "=f"(r) : "f"(x)); return r;
}

__device__ __forceinline__ float focal_cc2(float p) {
    float ip  = 1.0f - p;
    float pos = 0.25f * ip * ip * (-__logf(p  + 1e-8f));
    float neg = 0.75f * p  * p  * (-__logf(ip + 1e-8f));
    return pos - neg + 2.0f;          // +2 from GIoU algebra folded in
}

// ---------------------------------------------------------------------------
// Kernel 1: blocks [0,450): 32 warps = 32 rows; softmax + focal table,
// transposed through smem, written coalesced as [class][row-in-block].
// Block 450: target precompute (cwh + packed classes).
// ---------------------------------------------------------------------------
__global__ void __launch_bounds__(1024)
prep(const float* __restrict__ logits,
     const float* __restrict__ tbox,
     const int*   __restrict__ tids) {
    if (blockIdx.x < RBLK) {
        __shared__ float s_t[NCLS * 33];   // [class][row] padded
        int w    = threadIdx.x >> 5;       // warp = row-in-block
        int lane = threadIdx.x & 31;
        int row  = blockIdx.x * BR + w;

        float4 l = ((const float4*)(logits + (size_t)row * NCLS))[lane];

        float m = fmaxf(fmaxf(l.x, l.y), fmaxf(l.z, l.w));
        #pragma unroll
        for (int o = 16; o > 0; o >>= 1) m = fmaxf(m, __shfl_xor_sync(0xffffffffu, m, o));

        float ex = __expf(l.x - m), ey = __expf(l.y - m);
        float ez = __expf(l.z - m), ew = __expf(l.w - m);
        float s = ex + ey + ez + ew;
        #pragma unroll
        for (int o = 16; o > 0; o >>= 1) s += __shfl_xor_sync(0xffffffffu, s, o);
        float rs = __fdividef(1.0f, s);

        int c0 = lane * 4;
        s_t[(c0 + 0) * 33 + w] = focal_cc2(ex * rs);
        s_t[(c0 + 1) * 33 + w] = focal_cc2(ey * rs);
        s_t[(c0 + 2) * 33 + w] = focal_cc2(ez * rs);
        s_t[(c0 + 3) * 33 + w] = focal_cc2(ew * rs);
        __syncthreads();

        // coalesced write-out: float4 over rows, class-major
        int tid = threadIdx.x;
        int c  = tid >> 3;
        int r0 = (tid & 7) * 4;
        const float* p = s_t + c * 33 + r0;
        float4 v = make_float4(p[0], p[1], p[2], p[3]);
        ((float4*)g_ccostT)[(size_t)blockIdx.x * 1024 + tid] = v;
    } else {
        int t4 = threadIdx.x;
        if (t4 < NTGT / 4) {
            int4 ids = ((const int4*)tids)[t4];
            unsigned pk = (unsigned)(min(max(ids.x, 0), NCLS - 1))
                        | ((unsigned)(min(max(ids.y, 0), NCLS - 1)) << 8)
                        | ((unsigned)(min(max(ids.z, 0), NCLS - 1)) << 16)
                        | ((unsigned)(min(max(ids.w, 0), NCLS - 1)) << 24);
            g_tcl4[t4] = pk;
            #pragma unroll
            for (int m = 0; m < 4; m++)
                g_tcwh[t4 * 4 + m] = ((const float4*)tbox)[t4 * 4 + m];
        }
    }
}

// ---------------------------------------------------------------------------
// Kernel 2: main cost matrix. Grid (25, 450), 256 threads.
// tx = tid&31 -> 4 contiguous targets (STG.128); ty = tid>>5 -> 4 rows.
// cc table transposed: one LDS.128 = class cost for all 4 rows.
// ---------------------------------------------------------------------------
__global__ void __launch_bounds__(256, 4)
cost_main(const float* __restrict__ pboxes,
          float* __restrict__ out) {
    __shared__ float    s_cc[NCLS * CPAD];  // 18.4 KB, [class][row] pad-36
    __shared__ float4   s_tc[BT];           // cwh
    __shared__ unsigned s_tcl4[BT / 4];

    int tid = threadIdx.x;
    int tb  = blockIdx.x * BT;
    int rb  = blockIdx.y;                   // 32-row block index

    // Stage transposed cc table: 1024 float4, 4 per thread, conflict-free STS
    {
        const float4* src = (const float4*)g_ccostT + (size_t)rb * 1024;
        #pragma unroll
        for (int k = 0; k < 4; k++) {
            int f  = tid + k * 256;
            int c  = f >> 3;
            int rq = f & 7;
            *(float4*)(s_cc + c * CPAD + rq * 4) = src[f];
        }
    }
    if (tid < BT)     s_tc[tid]   = g_tcwh[tb + tid];
    if (tid < BT / 4) s_tcl4[tid] = g_tcl4[(tb >> 2) + tid];
    __syncthreads();

    int tx = tid & 31, ty = tid >> 5;
    int r0 = rb * BR + ty * 4;
    int t0 = tx * 4;

    // Row operands (persistent): 9 x 4 regs
    float rx0[4], ry0[4], rx1[4], ry1[4];
    float rcx[4], rcy[4], rw[4], rh[4], ra[4];
    #pragma unroll
    for (int i = 0; i < 4; i++) {
        float4 b = ((const float4*)pboxes)[r0 + i];
        rcx[i] = b.x; rcy[i] = b.y; rw[i] = b.z; rh[i] = b.w;
        float hw = 0.5f * b.z, hh = 0.5f * b.w;
        rx0[i] = b.x - hw; ry0[i] = b.y - hh;
        rx1[i] = b.x + hw; ry1[i] = b.y + hh;
        ra[i]  = b.z * b.w;
    }

    float o[4][4];
    unsigned cls4 = s_tcl4[tx];

    #pragma unroll
    for (int j = 0; j < 4; j++) {
        // Target operands (transient)
        float4 c = s_tc[t0 + j];
        float thw = 0.5f * c.z, thh = 0.5f * c.w;
        float tX0 = c.x - thw, tY0 = c.y - thh;
        float tX1 = c.x + thw, tY1 = c.y + thh;
        float ta  = c.z * c.w;
        int cls = (cls4 >> (8 * j)) & 255;

        // class cost (+2) for all 4 rows in one LDS.128
        float4 ccv = *(const float4*)(s_cc + cls * CPAD + ty * 4);
        const float* ccp = &ccv.x;

        #pragma unroll
        for (int i = 0; i < 4; i++) {
            // L1 (cxcywh)
            float l1 = (fabsf(rcx[i] - c.x) + fabsf(rcy[i] - c.y))
                     + (fabsf(rw[i]  - c.z) + fabsf(rh[i]  - c.w));

            // intersection span (may be negative)
            float ltx = fmaxf(rx0[i], tX0);
            float lty = fmaxf(ry0[i], tY0);
            float rbx = fminf(rx1[i], tX1);
            float rby = fminf(ry1[i], tY1);
            float sx  = rbx - ltx;
            float sy  = rby - lty;
            float inter = fmaxf(sx, 0.0f) * fmaxf(sy, 0.0f);

            // enclosure via identity: encl = w_r + w_t - span
            float ex = (rw[i] + c.z) - sx;
            float ey = (rh[i] + c.w) - sy;
            float ai = ex * ey;

            float uni = (ra[i] + ta) - inter;

            // C = 5*l1 + (cc+2) - 2*inter/uni - 2*uni/ai
            float iou = inter * frcp(uni);
            float q   = uni * frcp(ai);
            float res = fmaf(l1, 5.0f, ccp[i]);  // FFMA-imm
            res = fmaf(iou, -2.0f, res);         // FFMA-imm
            res = fmaf(q,   -2.0f, res);         // FFMA-imm
            o[i][j] = res;
        }
    }

    #pragma unroll
    for (int i = 0; i < 4; i++) {
        float4 v = make_float4(o[i][0], o[i][1], o[i][2], o[i][3]);
        *((float4*)(out + (size_t)(r0 + i) * NTGT + tb + t0)) = v;
    }
}

// ---------------------------------------------------------------------------
extern "C" void kernel_launch(void* const* d_in, const int* in_sizes, int n_in,
                              void* d_out, int out_size) {
    const float* logits = (const float*)d_in[0];      // [16,900,128]
    const float* pboxes = (const float*)d_in[1];      // [16,900,4]
    const int*   tids   = (const int*)d_in[2];        // [3200] int32
    const float* tbox   = (const float*)d_in[3];      // [3200,4]
    float* out = (float*)d_out;                       // [16,900,3200]

    prep<<<RBLK + 1, 1024>>>(logits, tbox, tids);

    dim3 grid(NTGT / BT, RBLK);                       // (25, 450)
    cost_main<<<grid, 256>>>(pboxes, out);
}